// round 16
// baseline (speedup 1.0000x reference)
#include <cuda_runtime.h>
#include <math.h>

// CPPN fused MLP. R14 kernel, resubmit (broker infra failure; delta
// unmeasured). j-blocked layers, 1 pt/thread, TPB=512, LDS.128.
// Evidence: fma-busy invariant ~6.06e6 cyc across all tanh/LDS variants =>
// FFMA2 is issue-compression only (fp32 pipe wall ~3.0-3.3ms); goal is pipe
// utilization (57% -> ~85%). R12/R13 spilled (regs at cap, DRAM 7.6%/12.8%).
// Fix: split each layer into 2 j-blocks of 16 outputs (8 u64 accs) writing a
// separate output array (ping-pong across layer pairs): hot regs ~95 (no
// spills at 128 cap), and block0's tanh chain overlaps block1's FFMA2 k-loop
// (intra-warp ILP across phases). Math identical to R3: accurate tanhf +
// accurate sigmoid; per-output accumulation order unchanged.

#define DH    32
#define NHID  22
#define TPB   512
#define GRID  148
#define SWH_F (NHID * DH * DH)                   // 22528
#define SW1_F (11 * DH)                          // 352
#define SWO_F (DH * 4)                           // 128
#define SMEM_BYTES ((SWH_F + SW1_F + SWO_F) * 4) // 92032 B

typedef unsigned long long u64;

__device__ __forceinline__ u64 dup2(float v) {
    u64 r; asm("mov.b64 %0, {%1, %1};" : "=l"(r) : "f"(v)); return r;
}
__device__ __forceinline__ void ffma2(u64& acc, u64 a, u64 b) {
    asm("fma.rn.f32x2 %0, %1, %2, %0;" : "+l"(acc) : "l"(a), "l"(b));
}
__device__ __forceinline__ void unpk(u64 v, float& lo, float& hi) {
    asm("mov.b64 {%0, %1}, %2;" : "=f"(lo), "=f"(hi) : "l"(v));
}
__device__ __forceinline__ float sigmoidf_acc(float v) {
    return 1.0f / (1.0f + expf(-v));
}

// One hidden layer, single point, j-blocked: hout = tanh(W * hin).
// W k-major in shared ([k][32j] floats = [k][8] 16B quads).
// Block b covers outputs j = b*16 .. b*16+15 (quads b*4 .. b*4+3).
__device__ __forceinline__ void hidden_layer(const float* wbase,
                                             const float* hin, float* hout) {
    const ulonglong2* w2 = (const ulonglong2*)wbase;
    #pragma unroll
    for (int b = 0; b < 2; b++) {
        u64 a[8];
        #pragma unroll
        for (int j = 0; j < 8; j++) a[j] = 0ull;
        #pragma unroll
        for (int k = 0; k < DH; k++) {
            u64 a2 = dup2(hin[k]);
            #pragma unroll
            for (int jj = 0; jj < 4; jj++) {
                ulonglong2 wv = w2[k * 8 + b * 4 + jj];
                ffma2(a[2 * jj],     a2, wv.x);
                ffma2(a[2 * jj + 1], a2, wv.y);
            }
        }
        #pragma unroll
        for (int j = 0; j < 8; j++) {
            float lo, hi; unpk(a[j], lo, hi);
            hout[b * 16 + 2 * j]     = tanhf(lo);
            hout[b * 16 + 2 * j + 1] = tanhf(hi);
        }
    }
}

__global__ void __launch_bounds__(TPB, 1)
cppn_kernel(const float* __restrict__ x,
            const float* __restrict__ W1,
            const float* __restrict__ Wh,
            const float* __restrict__ Wo,
            float* __restrict__ out, int n)
{
    extern __shared__ float sm[];
    float* sWh = sm;                 // [L][k][j], j contiguous, 16B aligned
    float* sW1 = sm + SWH_F;         // [k][j]
    float* sWo = sW1 + SW1_F;        // [k][4]  (o = 0..2, o=3 pad)

    for (int idx = threadIdx.x; idx < SWH_F; idx += TPB) {
        int L = idx >> 10, r = idx & 1023, j = r >> 5, k = r & 31;
        sWh[(L << 10) + (k << 5) + j] = Wh[idx];
    }
    for (int idx = threadIdx.x; idx < DH * 11; idx += TPB) {
        int j = idx / 11, k = idx - j * 11;
        sW1[k * DH + j] = W1[idx];
    }
    for (int idx = threadIdx.x; idx < 4 * DH; idx += TPB) {
        int k = idx >> 2, o = idx & 3;
        sWo[idx] = (o < 3) ? Wo[o * DH + k] : 0.0f;
    }
    __syncthreads();

    const int stride = GRID * TPB;
    for (int p = blockIdx.x * TPB + (int)threadIdx.x; p < n; p += stride) {
        float hA[DH], hB[DH];

        // ---------------- layer 1: 11 -> 32, tanh (j-blocked) --------------
        {
            float xv[11];
            #pragma unroll
            for (int k = 0; k < 11; k++) xv[k] = x[p * 11 + k];
            const ulonglong2* w2 = (const ulonglong2*)sW1;
            #pragma unroll
            for (int b = 0; b < 2; b++) {
                u64 a[8];
                #pragma unroll
                for (int j = 0; j < 8; j++) a[j] = 0ull;
                #pragma unroll
                for (int k = 0; k < 11; k++) {
                    u64 a2 = dup2(xv[k]);
                    #pragma unroll
                    for (int jj = 0; jj < 4; jj++) {
                        ulonglong2 wv = w2[k * 8 + b * 4 + jj];
                        ffma2(a[2 * jj],     a2, wv.x);
                        ffma2(a[2 * jj + 1], a2, wv.y);
                    }
                }
                #pragma unroll
                for (int j = 0; j < 8; j++) {
                    float lo, hi; unpk(a[j], lo, hi);
                    hA[b * 16 + 2 * j]     = tanhf(lo);
                    hA[b * 16 + 2 * j + 1] = tanhf(hi);
                }
            }
        }

        // ------------- 22 hidden layers: ping-pong hA <-> hB ---------------
        #pragma unroll 1
        for (int L = 0; L < NHID; L += 2) {
            hidden_layer(sWh + (L << 10),       hA, hB);
            hidden_layer(sWh + ((L + 1) << 10), hB, hA);
        }

        // ---------------- output: 32 -> 3, sigmoid ----------------
        {
            const u64* w = (const u64*)sWo;   // [k][2] u64 per row
            u64 o0 = 0ull, o1 = 0ull;
            #pragma unroll
            for (int k = 0; k < DH; k++) {
                u64 a2 = dup2(hA[k]);
                ffma2(o0, a2, w[2 * k]);
                ffma2(o1, a2, w[2 * k + 1]);
            }
            float r0, r1, r2, rpad;
            unpk(o0, r0, r1); unpk(o1, r2, rpad);
            out[3 * p + 0] = sigmoidf_acc(r0);
            out[3 * p + 1] = sigmoidf_acc(r1);
            out[3 * p + 2] = sigmoidf_acc(r2);
        }
    }
}

extern "C" void kernel_launch(void* const* d_in, const int* in_sizes, int n_in,
                              void* d_out, int out_size)
{
    const float* x  = (const float*)d_in[0];
    const float* W1 = (const float*)d_in[1];
    const float* Wh = (const float*)d_in[2];
    const float* Wo = (const float*)d_in[3];
    float* out = (float*)d_out;

    const int n = in_sizes[0] / 11;

    cudaFuncSetAttribute(cppn_kernel,
                         cudaFuncAttributeMaxDynamicSharedMemorySize,
                         SMEM_BYTES);
    cppn_kernel<<<GRID, TPB, SMEM_BYTES>>>(x, W1, Wh, Wo, out, n);
}

// round 17
// speedup vs baseline: 1.0003x; 1.0003x over previous
#include <cuda_runtime.h>
#include <math.h>

// CPPN fused MLP. R14 kernel, resubmit (broker infra failure; delta
// unmeasured). j-blocked layers, 1 pt/thread, TPB=512, LDS.128.
// Evidence: fma-busy invariant ~6.06e6 cyc across all tanh/LDS variants =>
// FFMA2 is issue-compression only (fp32 pipe wall ~3.0-3.3ms); goal is pipe
// utilization (57% -> ~85%). R12/R13 spilled (regs at cap, DRAM 7.6%/12.8%).
// Fix: split each layer into 2 j-blocks of 16 outputs (8 u64 accs) writing a
// separate output array (ping-pong across layer pairs): hot regs ~95 (no
// spills at 128 cap), and block0's tanh chain overlaps block1's FFMA2 k-loop
// (intra-warp ILP across phases). Math identical to R3: accurate tanhf +
// accurate sigmoid; per-output accumulation order unchanged.

#define DH    32
#define NHID  22
#define TPB   512
#define GRID  148
#define SWH_F (NHID * DH * DH)                   // 22528
#define SW1_F (11 * DH)                          // 352
#define SWO_F (DH * 4)                           // 128
#define SMEM_BYTES ((SWH_F + SW1_F + SWO_F) * 4) // 92032 B

typedef unsigned long long u64;

__device__ __forceinline__ u64 dup2(float v) {
    u64 r; asm("mov.b64 %0, {%1, %1};" : "=l"(r) : "f"(v)); return r;
}
__device__ __forceinline__ void ffma2(u64& acc, u64 a, u64 b) {
    asm("fma.rn.f32x2 %0, %1, %2, %0;" : "+l"(acc) : "l"(a), "l"(b));
}
__device__ __forceinline__ void unpk(u64 v, float& lo, float& hi) {
    asm("mov.b64 {%0, %1}, %2;" : "=f"(lo), "=f"(hi) : "l"(v));
}
__device__ __forceinline__ float sigmoidf_acc(float v) {
    return 1.0f / (1.0f + expf(-v));
}

// One hidden layer, single point, j-blocked: hout = tanh(W * hin).
// W k-major in shared ([k][32j] floats = [k][8] 16B quads).
// Block b covers outputs j = b*16 .. b*16+15 (quads b*4 .. b*4+3).
__device__ __forceinline__ void hidden_layer(const float* wbase,
                                             const float* hin, float* hout) {
    const ulonglong2* w2 = (const ulonglong2*)wbase;
    #pragma unroll
    for (int b = 0; b < 2; b++) {
        u64 a[8];
        #pragma unroll
        for (int j = 0; j < 8; j++) a[j] = 0ull;
        #pragma unroll
        for (int k = 0; k < DH; k++) {
            u64 a2 = dup2(hin[k]);
            #pragma unroll
            for (int jj = 0; jj < 4; jj++) {
                ulonglong2 wv = w2[k * 8 + b * 4 + jj];
                ffma2(a[2 * jj],     a2, wv.x);
                ffma2(a[2 * jj + 1], a2, wv.y);
            }
        }
        #pragma unroll
        for (int j = 0; j < 8; j++) {
            float lo, hi; unpk(a[j], lo, hi);
            hout[b * 16 + 2 * j]     = tanhf(lo);
            hout[b * 16 + 2 * j + 1] = tanhf(hi);
        }
    }
}

__global__ void __launch_bounds__(TPB, 1)
cppn_kernel(const float* __restrict__ x,
            const float* __restrict__ W1,
            const float* __restrict__ Wh,
            const float* __restrict__ Wo,
            float* __restrict__ out, int n)
{
    extern __shared__ float sm[];
    float* sWh = sm;                 // [L][k][j], j contiguous, 16B aligned
    float* sW1 = sm + SWH_F;         // [k][j]
    float* sWo = sW1 + SW1_F;        // [k][4]  (o = 0..2, o=3 pad)

    for (int idx = threadIdx.x; idx < SWH_F; idx += TPB) {
        int L = idx >> 10, r = idx & 1023, j = r >> 5, k = r & 31;
        sWh[(L << 10) + (k << 5) + j] = Wh[idx];
    }
    for (int idx = threadIdx.x; idx < DH * 11; idx += TPB) {
        int j = idx / 11, k = idx - j * 11;
        sW1[k * DH + j] = W1[idx];
    }
    for (int idx = threadIdx.x; idx < 4 * DH; idx += TPB) {
        int k = idx >> 2, o = idx & 3;
        sWo[idx] = (o < 3) ? Wo[o * DH + k] : 0.0f;
    }
    __syncthreads();

    const int stride = GRID * TPB;
    for (int p = blockIdx.x * TPB + (int)threadIdx.x; p < n; p += stride) {
        float hA[DH], hB[DH];

        // ---------------- layer 1: 11 -> 32, tanh (j-blocked) --------------
        {
            float xv[11];
            #pragma unroll
            for (int k = 0; k < 11; k++) xv[k] = x[p * 11 + k];
            const ulonglong2* w2 = (const ulonglong2*)sW1;
            #pragma unroll
            for (int b = 0; b < 2; b++) {
                u64 a[8];
                #pragma unroll
                for (int j = 0; j < 8; j++) a[j] = 0ull;
                #pragma unroll
                for (int k = 0; k < 11; k++) {
                    u64 a2 = dup2(xv[k]);
                    #pragma unroll
                    for (int jj = 0; jj < 4; jj++) {
                        ulonglong2 wv = w2[k * 8 + b * 4 + jj];
                        ffma2(a[2 * jj],     a2, wv.x);
                        ffma2(a[2 * jj + 1], a2, wv.y);
                    }
                }
                #pragma unroll
                for (int j = 0; j < 8; j++) {
                    float lo, hi; unpk(a[j], lo, hi);
                    hA[b * 16 + 2 * j]     = tanhf(lo);
                    hA[b * 16 + 2 * j + 1] = tanhf(hi);
                }
            }
        }

        // ------------- 22 hidden layers: ping-pong hA <-> hB ---------------
        #pragma unroll 1
        for (int L = 0; L < NHID; L += 2) {
            hidden_layer(sWh + (L << 10),       hA, hB);
            hidden_layer(sWh + ((L + 1) << 10), hB, hA);
        }

        // ---------------- output: 32 -> 3, sigmoid ----------------
        {
            const u64* w = (const u64*)sWo;   // [k][2] u64 per row
            u64 o0 = 0ull, o1 = 0ull;
            #pragma unroll
            for (int k = 0; k < DH; k++) {
                u64 a2 = dup2(hA[k]);
                ffma2(o0, a2, w[2 * k]);
                ffma2(o1, a2, w[2 * k + 1]);
            }
            float r0, r1, r2, rpad;
            unpk(o0, r0, r1); unpk(o1, r2, rpad);
            out[3 * p + 0] = sigmoidf_acc(r0);
            out[3 * p + 1] = sigmoidf_acc(r1);
            out[3 * p + 2] = sigmoidf_acc(r2);
        }
    }
}

extern "C" void kernel_launch(void* const* d_in, const int* in_sizes, int n_in,
                              void* d_out, int out_size)
{
    const float* x  = (const float*)d_in[0];
    const float* W1 = (const float*)d_in[1];
    const float* Wh = (const float*)d_in[2];
    const float* Wo = (const float*)d_in[3];
    float* out = (float*)d_out;

    const int n = in_sizes[0] / 11;

    cudaFuncSetAttribute(cppn_kernel,
                         cudaFuncAttributeMaxDynamicSharedMemorySize,
                         SMEM_BYTES);
    cppn_kernel<<<GRID, TPB, SMEM_BYTES>>>(x, W1, Wh, Wo, out, n);
}